// round 9
// baseline (speedup 1.0000x reference)
#include <cuda_runtime.h>
#include <cstdint>

// MergedEmbeddingBag: T=26 tables, R=100000 rows, D=128, B=4096 bags/table, L=20 bag size.
// Pooling: even tables SUM, odd tables MEAN (scale 1/L).
// Inputs: d_in[0] = W [T,R,D] float32, d_in[1] = indices [T,B,L] int32.
// Output: [T,B,D] float32.
//
// R5 analysis: DRAM traffic is at the compulsory floor (~808 MB); L2 dedup is
// already maximal (hit rate == duplicate fraction). Only serial-latency bubbles
// remain. This round: front-load ALL 20 indices before any gather, so the
// second gather batch never waits on an index fetch round-trip.

constexpr int T = 26;
constexpr int R = 100000;
constexpr int D = 128;
constexpr int B = 4096;
constexpr int L = 20;
constexpr int HALF = L / 2;   // 10

__global__ __launch_bounds__(256, 3) void merged_embedding_bag_kernel(
    const float* __restrict__ W,
    const int* __restrict__ indices,
    float* __restrict__ out)
{
    const int gwarp = (blockIdx.x * blockDim.x + threadIdx.x) >> 5;
    const int lane  = threadIdx.x & 31;
    if (gwarp >= T * B) return;

    const int t = gwarp / B;
    const int b = gwarp - t * B;

    const int* __restrict__ bag = indices + ((size_t)t * B + b) * L;
    const float* __restrict__ Wt = W + (size_t)t * R * D;

    // All 20 indices fetched up front (warp-uniform broadcast loads, fully
    // overlapped). After this, no gather ever waits on an index round-trip.
    int idx[L];
#pragma unroll
    for (int j = 0; j < L; j++) idx[j] = __ldg(bag + j);

    float4 acc = make_float4(0.f, 0.f, 0.f, 0.f);
    float4 v[HALF];

    // ---- batch 1: 10 independent gathers live in registers ----
#pragma unroll
    for (int j = 0; j < HALF; j++)
        v[j] = __ldg(reinterpret_cast<const float4*>(Wt + (size_t)idx[j] * D) + lane);
#pragma unroll
    for (int j = 0; j < HALF; j++) {
        acc.x += v[j].x; acc.y += v[j].y; acc.z += v[j].z; acc.w += v[j].w;
    }

    // ---- batch 2: indices already resident; loads issue as v[] regs free ----
#pragma unroll
    for (int j = 0; j < HALF; j++)
        v[j] = __ldg(reinterpret_cast<const float4*>(Wt + (size_t)idx[HALF + j] * D) + lane);
#pragma unroll
    for (int j = 0; j < HALF; j++) {
        acc.x += v[j].x; acc.y += v[j].y; acc.z += v[j].z; acc.w += v[j].w;
    }

    const float s = (t & 1) ? (1.0f / (float)L) : 1.0f;
    acc.x *= s; acc.y *= s; acc.z *= s; acc.w *= s;

    // Streaming store: output lines are dead after write.
    float4* o = reinterpret_cast<float4*>(out + ((size_t)t * B + b) * D) + lane;
    __stcs(o, acc);
}

extern "C" void kernel_launch(void* const* d_in, const int* in_sizes, int n_in,
                              void* d_out, int out_size)
{
    const float* W = (const float*)d_in[0];
    const int* indices = (const int*)d_in[1];
    float* out = (float*)d_out;

    const int total_warps = T * B;               // 106496
    const int threads = 256;                     // 8 warps / block
    const int blocks = (total_warps * 32 + threads - 1) / threads;  // 13312

    merged_embedding_bag_kernel<<<blocks, threads>>>(W, indices, out);
}

// round 13
// speedup vs baseline: 1.0361x; 1.0361x over previous
#include <cuda_runtime.h>
#include <cstdint>

// MergedEmbeddingBag: T=26 tables, R=100000 rows, D=128, B=4096 bags/table, L=20 bag size.
// Pooling: even tables SUM, odd tables MEAN (scale 1/L).
// Inputs: d_in[0] = W [T,R,D] float32, d_in[1] = indices [T,B,L] int32.
// Output: [T,B,D] float32.
//
// R9 analysis: DRAM busy% tracks (occupancy x per-warp MLP); registers bind that
// product at ~280. This round: cp.async (LDGSTS) stages gathered rows in SMEM,
// giving MLP depth with no destination registers -> occ 62.5% x MLP 10 = 400.

constexpr int T = 26;
constexpr int R = 100000;
constexpr int D = 128;
constexpr int B = 4096;
constexpr int L = 20;

constexpr int WARPS_PER_BLOCK = 8;
constexpr int STAGE_ROWS = 10;   // staged rows per warp (two 5-row groups)
constexpr int GRP = 5;           // rows per cp.async commit group

__device__ __forceinline__ void cp_async16(uint32_t dst_smem, const void* src) {
    asm volatile("cp.async.cg.shared.global [%0], [%1], 16;\n"
                 :: "r"(dst_smem), "l"(src) : "memory");
}
__device__ __forceinline__ void cp_commit() {
    asm volatile("cp.async.commit_group;\n" ::: "memory");
}
template <int N>
__device__ __forceinline__ void cp_wait() {
    asm volatile("cp.async.wait_group %0;\n" :: "n"(N) : "memory");
}

__global__ __launch_bounds__(256, 5) void merged_embedding_bag_kernel(
    const float* __restrict__ W,
    const int* __restrict__ indices,
    float* __restrict__ out)
{
    __shared__ float4 stage[WARPS_PER_BLOCK][STAGE_ROWS][32];  // 40 KB

    const int gwarp = (blockIdx.x * blockDim.x + threadIdx.x) >> 5;
    const int wwarp = threadIdx.x >> 5;
    const int lane  = threadIdx.x & 31;
    if (gwarp >= T * B) return;

    const int t = gwarp / B;
    const int b = gwarp - t * B;

    const int* __restrict__ bag = indices + ((size_t)t * B + b) * L;
    const float* __restrict__ Wt = W + (size_t)t * R * D;

    // All 20 indices up front (warp-uniform broadcast loads, fully overlapped).
    int idx[L];
#pragma unroll
    for (int j = 0; j < L; j++) idx[j] = __ldg(bag + j);

    // Each thread stages/reads ONLY its own lane's float4 -> no cross-thread
    // smem sharing, no syncwarp needed.
    uint32_t sbase = (uint32_t)__cvta_generic_to_shared(&stage[wwarp][0][lane]);
    const uint32_t srow = 32 * sizeof(float4);  // stride between staged rows

    auto issue_group = [&](int slot0, int j0) {
#pragma unroll
        for (int k = 0; k < GRP; k++) {
            const float* src = Wt + (size_t)idx[j0 + k] * D + lane * 4;
            cp_async16(sbase + (slot0 + k) * srow, src);
        }
        cp_commit();
    };

    float4 acc = make_float4(0.f, 0.f, 0.f, 0.f);
    auto accum_group = [&](int slot0) {
#pragma unroll
        for (int k = 0; k < GRP; k++) {
            float4 v = stage[wwarp][slot0 + k][lane];
            acc.x += v.x; acc.y += v.y; acc.z += v.z; acc.w += v.w;
        }
    };

    // 4-group pipeline over 20 rows, 2 groups (10 rows) in flight.
    issue_group(0, 0);      // G0 -> slots 0-4
    issue_group(GRP, GRP);  // G1 -> slots 5-9

    cp_wait<1>();           // G0 ready
    accum_group(0);
    issue_group(0, 10);     // G2 -> slots 0-4

    cp_wait<1>();           // G1 ready (G2 may be in flight)
    accum_group(GRP);
    issue_group(GRP, 15);   // G3 -> slots 5-9

    cp_wait<1>();           // G2 ready
    accum_group(0);

    cp_wait<0>();           // G3 ready
    accum_group(GRP);

    const float s = (t & 1) ? (1.0f / (float)L) : 1.0f;
    acc.x *= s; acc.y *= s; acc.z *= s; acc.w *= s;

    // Streaming store: output lines are dead after write.
    float4* o = reinterpret_cast<float4*>(out + ((size_t)t * B + b) * D) + lane;
    __stcs(o, acc);
}

extern "C" void kernel_launch(void* const* d_in, const int* in_sizes, int n_in,
                              void* d_out, int out_size)
{
    const float* W = (const float*)d_in[0];
    const int* indices = (const int*)d_in[1];
    float* out = (float*)d_out;

    const int total_warps = T * B;               // 106496
    const int threads = 256;                     // 8 warps / block
    const int blocks = (total_warps * 32 + threads - 1) / threads;  // 13312

    merged_embedding_bag_kernel<<<blocks, threads>>>(W, indices, out);
}